// round 4
// baseline (speedup 1.0000x reference)
#include <cuda_runtime.h>
#include <cstdint>
#include <cstddef>

#define FULLMASK 0xffffffffu

#define B_   16
#define N_   8192
#define CIN  64
#define CTOT 67
#define M_   1024
#define KK   32
#define HID  64
#define OUTC 128
#define SPAT (M_*KK)
#define EPSV 1e-5f

// ---------------- device scratch (static, no allocation) ----------------
__device__ int   g_knn[B_*M_*KK];                       // 2 MB
__device__ float g_x1[(size_t)B_*HID*SPAT];             // 134 MB
__device__ float g_x2[(size_t)B_*OUTC*SPAT];            // 268 MB
__device__ float g_cs1[B_*HID*2];                       // per-channel sum/sumsq
__device__ float g_cs2[B_*OUTC*2];
__device__ float g_centfb[B_*M_*3];                     // fallback centroid buffer

// ---------------- helpers ----------------
__device__ __forceinline__ unsigned redux_max_u32(unsigned v) {
    unsigned r;
    asm volatile("redux.sync.max.u32 %0, %1, 0xffffffff;" : "=r"(r) : "r"(v));
    return r;
}
__device__ __forceinline__ unsigned redux_min_u32(unsigned v) {
    unsigned r;
    asm volatile("redux.sync.min.u32 %0, %1, 0xffffffff;" : "=r"(r) : "r"(v));
    return r;
}
__device__ __forceinline__ int redux_max_s32(int v) {
    int r;
    asm volatile("redux.sync.max.s32 %0, %1, 0xffffffff;" : "=r"(r) : "r"(v));
    return r;
}

// monotonic total-order key for float (handles negatives from cancellation)
__device__ __forceinline__ unsigned f2key(float f) {
    unsigned u = __float_as_uint(f);
    unsigned mask = ((unsigned)((int)u >> 31)) | 0x80000000u;
    return u ^ mask;
}

__device__ __forceinline__ float2 blk_reduce2(float s, float s2) {
    const int lane = threadIdx.x & 31, w = threadIdx.x >> 5;
    #pragma unroll
    for (int o = 16; o; o >>= 1) {
        s  += __shfl_down_sync(FULLMASK, s,  o);
        s2 += __shfl_down_sync(FULLMASK, s2, o);
    }
    __shared__ float rs[8], rq[8];
    if (lane == 0) { rs[w] = s; rq[w] = s2; }
    __syncthreads();
    if (w == 0) {
        s  = (lane < 8) ? rs[lane] : 0.f;
        s2 = (lane < 8) ? rq[lane] : 0.f;
        #pragma unroll
        for (int o = 4; o; o >>= 1) {
            s  += __shfl_down_sync(FULLMASK, s,  o);
            s2 += __shfl_down_sync(FULLMASK, s2, o);
        }
    }
    return make_float2(s, s2);
}

// ---------------- K1: farthest point sampling ----------------
// one block per batch; xyz SoA in dynamic smem; dist in regs (8 pts/thread)
// Tie-break: argmax must return the LOWEST point index among ties (jnp.argmax).
__global__ void __launch_bounds__(1024, 1)
fps_kernel(const float* __restrict__ xyz, float* __restrict__ cent) {
    extern __shared__ float sm[];
    float* xs = sm; float* ys = sm + N_; float* zs = sm + 2 * N_;
    __shared__ unsigned swb[32];
    __shared__ unsigned swi[32];
    __shared__ float bc[3];
    const int b = blockIdx.x, t = threadIdx.x, lane = t & 31, w = t >> 5;
    const float* base = xyz + (size_t)b * N_ * 3;
    for (int p = t; p < N_; p += 1024) {
        xs[p] = base[3 * p]; ys[p] = base[3 * p + 1]; zs[p] = base[3 * p + 2];
    }
    __syncthreads();
    if (t == 0) {
        bc[0] = xs[0]; bc[1] = ys[0]; bc[2] = zs[0];
        size_t o = (size_t)b * M_ * 3;
        cent[o] = xs[0]; cent[o + 1] = ys[0]; cent[o + 2] = zs[0];
    }
    __syncthreads();
    float dist[8];
    #pragma unroll
    for (int j = 0; j < 8; j++) dist[j] = 1e10f;

    for (int it = 1; it < M_; ++it) {
        const float cx = bc[0], cy = bc[1], cz = bc[2];
        float mv = -1.f; int mi = t;
        #pragma unroll
        for (int j = 0; j < 8; j++) {
            const int p = t + j * 1024;
            // no fma-contraction: match reference mul/add rounding (argmax ties!)
            float dx = __fsub_rn(xs[p], cx);
            float dy = __fsub_rn(ys[p], cy);
            float dz = __fsub_rn(zs[p], cz);
            float d = __fadd_rn(__fadd_rn(__fmul_rn(dx, dx), __fmul_rn(dy, dy)),
                                __fmul_rn(dz, dz));
            float nd = fminf(dist[j], d);
            dist[j] = nd;
            // strict > keeps smallest p within this thread's ascending-p set
            if (nd > mv) { mv = nd; mi = p; }
        }
        unsigned mb = __float_as_uint(mv);          // dist >= 0 -> bits monotonic
        unsigned wm = redux_max_u32(mb);
        // among tied lanes pick the SMALLEST point index
        unsigned isel = (mb == wm) ? (unsigned)mi : 0xFFFFFFFFu;
        unsigned wi = redux_min_u32(isel);
        if (lane == 0) { swb[w] = wm; swi[w] = wi; }
        __syncthreads();
        if (w == 0) {
            unsigned vb = swb[lane]; unsigned vi = swi[lane];
            unsigned gm = redux_max_u32(vb);
            unsigned gsel = (vb == gm) ? vi : 0xFFFFFFFFu;
            unsigned far = redux_min_u32(gsel);
            if (lane == 0) {
                float fx = xs[far], fy = ys[far], fz = zs[far];
                bc[0] = fx; bc[1] = fy; bc[2] = fz;
                size_t o = ((size_t)b * M_ + it) * 3;
                cent[o] = fx; cent[o + 1] = fy; cent[o + 2] = fz;
            }
        }
        __syncthreads();
    }
}

// ---------------- K2: kNN top-32 (warp per centroid) ----------------
// top_k keeps lowest indices among value ties -> evict HIGHEST index among tied max
__global__ void __launch_bounds__(256, 1)
knn_kernel(const float* __restrict__ xyz, const float* __restrict__ cent) {
    extern __shared__ float sm[];
    float* xs = sm; float* ys = sm + N_; float* zs = sm + 2 * N_; float* xn = sm + 3 * N_;
    const int b = blockIdx.x, cb = blockIdx.y;
    const int t = threadIdx.x, lane = t & 31, w = t >> 5;
    const float* base = xyz + (size_t)b * N_ * 3;
    for (int p = t; p < N_; p += 256) {
        float x = base[3 * p], y = base[3 * p + 1], z = base[3 * p + 2];
        xs[p] = x; ys[p] = y; zs[p] = z;
        xn[p] = x * x + y * y + z * z;
    }
    __syncthreads();

    const int m0 = cb * 64 + w * 8;
    for (int mi = m0; mi < m0 + 8; ++mi) {
        size_t co = ((size_t)b * M_ + mi) * 3;
        float cx = cent[co], cy = cent[co + 1], cz = cent[co + 2];
        float cn = cx * cx + cy * cy + cz * cz;

        // init with points 0..31
        unsigned valkey; int vidx;
        {
            int p = lane;
            float d = cn + xn[p] - 2.f * (cx * xs[p] + cy * ys[p] + cz * zs[p]);
            valkey = f2key(d);
            vidx = p;
        }
        unsigned thr = redux_max_u32(valkey);

        for (int c0 = 32; c0 < N_; c0 += 32) {
            int p = c0 + lane;
            float d = cn + xn[p] - 2.f * (cx * xs[p] + cy * ys[p] + cz * zs[p]);
            unsigned dk = f2key(d);
            unsigned pend = __ballot_sync(FULLMASK, dk < thr);
            while (pend) {
                int src = __ffs(pend) - 1;
                pend &= pend - 1;
                unsigned dkj = __shfl_sync(FULLMASK, dk, src);
                if (dkj < thr) {
                    int pj = c0 + src;
                    unsigned vmax = redux_max_u32(valkey);
                    int cand = (valkey == vmax) ? vidx : -1;
                    int victimidx = redux_max_s32(cand);
                    if (valkey == vmax && vidx == victimidx) { valkey = dkj; vidx = pj; }
                    thr = redux_max_u32(valkey);
                }
            }
        }
        g_knn[((size_t)b * M_ + mi) * KK + lane] = vidx;
    }
}

// ---------------- K3: gather + conv1 (GEMM 64 x 64tile, Kdim=67) ----------------
__global__ void __launch_bounds__(256, 2)
conv1_kernel(const float* __restrict__ xyz, const float* __restrict__ feat,
             const float* __restrict__ w1, const float* __restrict__ b1,
             const float* __restrict__ cent) {
    __shared__ __align__(16) float Ws[CTOT * 64];   // [cin][cout]
    __shared__ __align__(16) float Xs[CTOT * 68];   // [cin][spatial(64)+pad]
    const int b = blockIdx.y, s0 = blockIdx.x * 64, tid = threadIdx.x;

    for (int i = tid; i < CTOT * 64; i += 256) {
        int cin = i >> 6, c = i & 63;
        Ws[i] = w1[c * CTOT + cin];
    }
    {
        const int ps = tid >> 2, r = tid & 3;
        const int s = s0 + ps, m = s >> 5, kk = s & 31;
        const int idx = g_knn[((size_t)b * M_ + m) * KK + kk];
        const float* fp = feat + ((size_t)b * N_ + idx) * CIN + r * 16;
        #pragma unroll
        for (int q = 0; q < 4; q++) {
            float4 v = *(const float4*)(fp + q * 4);
            int row = 3 + r * 16 + q * 4;
            Xs[(row + 0) * 68 + ps] = v.x;
            Xs[(row + 1) * 68 + ps] = v.y;
            Xs[(row + 2) * 68 + ps] = v.z;
            Xs[(row + 3) * 68 + ps] = v.w;
        }
        if (r == 0) {
            const float* xp = xyz + ((size_t)b * N_ + idx) * 3;
            const float* cp = cent + ((size_t)b * M_ + m) * 3;
            Xs[0 * 68 + ps] = xp[0] - cp[0];
            Xs[1 * 68 + ps] = xp[1] - cp[1];
            Xs[2 * 68 + ps] = xp[2] - cp[2];
        }
    }
    __syncthreads();

    const int ty = tid >> 4, tx = tid & 15;
    float acc[4][4];
    #pragma unroll
    for (int i = 0; i < 4; i++) {
        float bb = b1[ty * 4 + i];
        #pragma unroll
        for (int j = 0; j < 4; j++) acc[i][j] = bb;
    }
    #pragma unroll 4
    for (int cin = 0; cin < CTOT; cin++) {
        float4 a  = *(const float4*)&Ws[cin * 64 + ty * 4];
        float4 bv = *(const float4*)&Xs[cin * 68 + tx * 4];
        acc[0][0] += a.x * bv.x; acc[0][1] += a.x * bv.y; acc[0][2] += a.x * bv.z; acc[0][3] += a.x * bv.w;
        acc[1][0] += a.y * bv.x; acc[1][1] += a.y * bv.y; acc[1][2] += a.y * bv.z; acc[1][3] += a.y * bv.w;
        acc[2][0] += a.z * bv.x; acc[2][1] += a.z * bv.y; acc[2][2] += a.z * bv.z; acc[2][3] += a.z * bv.w;
        acc[3][0] += a.w * bv.x; acc[3][1] += a.w * bv.y; acc[3][2] += a.w * bv.z; acc[3][3] += a.w * bv.w;
    }
    #pragma unroll
    for (int i = 0; i < 4; i++) {
        int c = ty * 4 + i;
        float4 v = make_float4(acc[i][0], acc[i][1], acc[i][2], acc[i][3]);
        *(float4*)&g_x1[((size_t)b * HID + c) * SPAT + s0 + tx * 4] = v;
    }
}

// ---------------- K4/K6: per-channel stats (deterministic, no atomics) ----------------
__global__ void __launch_bounds__(256)
stats1_kernel() {
    const int bid = blockIdx.x, b = bid / HID, c = bid % HID;
    const float* p = g_x1 + ((size_t)b * HID + c) * SPAT;
    float s = 0.f, s2 = 0.f;
    for (int i = threadIdx.x; i < SPAT / 4; i += 256) {
        float4 v = ((const float4*)p)[i];
        s  += (v.x + v.y) + (v.z + v.w);
        s2 += (v.x * v.x + v.y * v.y) + (v.z * v.z + v.w * v.w);
    }
    float2 r = blk_reduce2(s, s2);
    if (threadIdx.x == 0) { g_cs1[bid * 2] = r.x; g_cs1[bid * 2 + 1] = r.y; }
}

__global__ void __launch_bounds__(256)
stats2_kernel() {
    const int bid = blockIdx.x, b = bid / OUTC, c = bid % OUTC;
    const float* p = g_x2 + ((size_t)b * OUTC + c) * SPAT;
    float s = 0.f, s2 = 0.f;
    for (int i = threadIdx.x; i < SPAT / 4; i += 256) {
        float4 v = ((const float4*)p)[i];
        s  += (v.x + v.y) + (v.z + v.w);
        s2 += (v.x * v.x + v.y * v.y) + (v.z * v.z + v.w * v.w);
    }
    float2 r = blk_reduce2(s, s2);
    if (threadIdx.x == 0) { g_cs2[bid * 2] = r.x; g_cs2[bid * 2 + 1] = r.y; }
}

// ---------------- K5: GN1+ReLU on load + conv2 (GEMM 128 x 64tile, Kdim=64) ----------------
__global__ void __launch_bounds__(256)
conv2_kernel(const float* __restrict__ w2, const float* __restrict__ b2,
             const float* __restrict__ g1w, const float* __restrict__ g1b) {
    extern __shared__ float dsm[];
    float* Ws2 = dsm;                  // 64*128
    float* Hs  = dsm + HID * OUTC;     // 64*68
    float* sc  = Hs + HID * 68;        // 64
    float* sh  = sc + HID;             // 64
    const int b = blockIdx.y, s0 = blockIdx.x * 64, tid = threadIdx.x;

    for (int i = tid; i < HID * OUTC; i += 256) {
        int cin = i >> 7, c = i & 127;
        Ws2[i] = w2[c * HID + cin];
    }
    if (tid < HID) {
        int c = tid, g = c >> 1, cb = b * HID + g * 2;
        float sum = g_cs1[cb * 2]     + g_cs1[(cb + 1) * 2];
        float sq  = g_cs1[cb * 2 + 1] + g_cs1[(cb + 1) * 2 + 1];
        float inv = 1.0f / 65536.0f;
        float mu = sum * inv;
        float var = sq * inv - mu * mu;
        float a = rsqrtf(var + EPSV) * g1w[c];
        sc[c] = a;
        sh[c] = g1b[c] - mu * a;
    }
    __syncthreads();
    {
        const int c = tid >> 2, sseg = (tid & 3) * 16;
        const float* p = g_x1 + ((size_t)b * HID + c) * SPAT + s0 + sseg;
        float a = sc[c], o = sh[c];
        #pragma unroll
        for (int q = 0; q < 4; q++) {
            float4 v = *(const float4*)(p + q * 4);
            Hs[c * 68 + sseg + q * 4 + 0] = fmaxf(fmaf(v.x, a, o), 0.f);
            Hs[c * 68 + sseg + q * 4 + 1] = fmaxf(fmaf(v.y, a, o), 0.f);
            Hs[c * 68 + sseg + q * 4 + 2] = fmaxf(fmaf(v.z, a, o), 0.f);
            Hs[c * 68 + sseg + q * 4 + 3] = fmaxf(fmaf(v.w, a, o), 0.f);
        }
    }
    __syncthreads();

    const int ty = tid >> 4, tx = tid & 15, c0 = ty * 8;
    float acc[8][4];
    #pragma unroll
    for (int i = 0; i < 8; i++) {
        float bb = b2[c0 + i];
        #pragma unroll
        for (int j = 0; j < 4; j++) acc[i][j] = bb;
    }
    #pragma unroll 4
    for (int cin = 0; cin < HID; cin++) {
        float4 a0 = *(const float4*)&Ws2[cin * OUTC + c0];
        float4 a1 = *(const float4*)&Ws2[cin * OUTC + c0 + 4];
        float4 bv = *(const float4*)&Hs[cin * 68 + tx * 4];
        acc[0][0] += a0.x * bv.x; acc[0][1] += a0.x * bv.y; acc[0][2] += a0.x * bv.z; acc[0][3] += a0.x * bv.w;
        acc[1][0] += a0.y * bv.x; acc[1][1] += a0.y * bv.y; acc[1][2] += a0.y * bv.z; acc[1][3] += a0.y * bv.w;
        acc[2][0] += a0.z * bv.x; acc[2][1] += a0.z * bv.y; acc[2][2] += a0.z * bv.z; acc[2][3] += a0.z * bv.w;
        acc[3][0] += a0.w * bv.x; acc[3][1] += a0.w * bv.y; acc[3][2] += a0.w * bv.z; acc[3][3] += a0.w * bv.w;
        acc[4][0] += a1.x * bv.x; acc[4][1] += a1.x * bv.y; acc[4][2] += a1.x * bv.z; acc[4][3] += a1.x * bv.w;
        acc[5][0] += a1.y * bv.x; acc[5][1] += a1.y * bv.y; acc[5][2] += a1.y * bv.z; acc[5][3] += a1.y * bv.w;
        acc[6][0] += a1.z * bv.x; acc[6][1] += a1.z * bv.y; acc[6][2] += a1.z * bv.z; acc[6][3] += a1.z * bv.w;
        acc[7][0] += a1.w * bv.x; acc[7][1] += a1.w * bv.y; acc[7][2] += a1.w * bv.z; acc[7][3] += a1.w * bv.w;
    }
    #pragma unroll
    for (int i = 0; i < 8; i++) {
        int c = c0 + i;
        float4 v = make_float4(acc[i][0], acc[i][1], acc[i][2], acc[i][3]);
        *(float4*)&g_x2[((size_t)b * OUTC + c) * SPAT + s0 + tx * 4] = v;
    }
}

// ---------------- K7: GN2 + ReLU + max over k ----------------
__global__ void __launch_bounds__(128)
final_kernel(const float* __restrict__ g2w, const float* __restrict__ g2b,
             float* __restrict__ out) {
    const int b = blockIdx.y, m = blockIdx.x, c = threadIdx.x, g = c >> 2;
    const int cb = b * OUTC + g * 4;
    float sum = 0.f, sq = 0.f;
    #pragma unroll
    for (int q = 0; q < 4; q++) {
        sum += g_cs2[(cb + q) * 2];
        sq  += g_cs2[(cb + q) * 2 + 1];
    }
    const float inv = 1.0f / 131072.0f;
    float mu = sum * inv;
    float var = sq * inv - mu * mu;
    float a = rsqrtf(var + EPSV) * g2w[c];
    float o = g2b[c] - mu * a;
    const float* p = g_x2 + ((size_t)b * OUTC + c) * SPAT + m * KK;
    float mx = 0.f;  // relu >= 0, so max(0, .) init is exact
    #pragma unroll
    for (int q = 0; q < 8; q++) {
        float4 v = *(const float4*)(p + q * 4);
        mx = fmaxf(mx, fmaf(v.x, a, o));
        mx = fmaxf(mx, fmaf(v.y, a, o));
        mx = fmaxf(mx, fmaf(v.z, a, o));
        mx = fmaxf(mx, fmaf(v.w, a, o));
    }
    out[((size_t)b * M_ + m) * OUTC + c] = mx;
}

// ---------------- launch ----------------
extern "C" void kernel_launch(void* const* d_in, const int* in_sizes, int n_in,
                              void* d_out, int out_size) {
    const float* xyz  = (const float*)d_in[0];
    const float* feat = (const float*)d_in[1];
    const float* w1   = (const float*)d_in[2];
    const float* b1   = (const float*)d_in[3];
    const float* g1w  = (const float*)d_in[4];
    const float* g1b  = (const float*)d_in[5];
    const float* w2   = (const float*)d_in[6];
    const float* b2   = (const float*)d_in[7];
    const float* g2w  = (const float*)d_in[8];
    const float* g2b  = (const float*)d_in[9];

    float* out = (float*)d_out;
    float* cent;
    float* nf;
    if (out_size == B_ * M_ * 3 + B_ * M_ * OUTC) {
        cent = out;
        nf = out + (size_t)B_ * M_ * 3;
    } else {
        // output is only new_feat; keep centroids in scratch
        void* p = nullptr;
        cudaGetSymbolAddress(&p, g_centfb);
        cent = (float*)p;
        nf = out;
    }

    cudaFuncSetAttribute(fps_kernel,  cudaFuncAttributeMaxDynamicSharedMemorySize, 3 * N_ * 4);
    cudaFuncSetAttribute(knn_kernel,  cudaFuncAttributeMaxDynamicSharedMemorySize, 4 * N_ * 4);
    cudaFuncSetAttribute(conv2_kernel, cudaFuncAttributeMaxDynamicSharedMemorySize,
                         (HID * OUTC + HID * 68 + 2 * HID) * 4);

    fps_kernel<<<B_, 1024, 3 * N_ * 4>>>(xyz, cent);
    knn_kernel<<<dim3(B_, 16), 256, 4 * N_ * 4>>>(xyz, cent);
    conv1_kernel<<<dim3(SPAT / 64, B_), 256>>>(xyz, feat, w1, b1, cent);
    stats1_kernel<<<B_ * HID, 256>>>();
    conv2_kernel<<<dim3(SPAT / 64, B_), 256,
                   (HID * OUTC + HID * 68 + 2 * HID) * 4>>>(w2, b2, g1w, g1b);
    stats2_kernel<<<B_ * OUTC, 256>>>();
    final_kernel<<<dim3(M_, B_), 128>>>(g2w, g2b, nf);
}

// round 5
// speedup vs baseline: 1.2388x; 1.2388x over previous
#include <cuda_runtime.h>
#include <cstdint>
#include <cstddef>

#define FULLMASK 0xffffffffu

#define B_   16
#define N_   8192
#define CIN  64
#define CTOT 67
#define M_   1024
#define KK   32
#define HID  64
#define OUTC 128
#define SPAT (M_*KK)
#define NBLK (SPAT/64)      // 512 conv tiles per batch
#define EPSV 1e-5f

// ---------------- device scratch (static, no allocation) ----------------
__device__ int   g_knn[B_*M_*KK];                       // 2 MB
__device__ float g_x1[(size_t)B_*HID*SPAT];             // 134 MB
__device__ float g_p1[B_*HID*NBLK*2];                   // 4 MB  conv1 partial sum/sumsq
__device__ float g_p2[B_*OUTC*NBLK*2];                  // 8 MB  conv2 partial sum/sumsq
__device__ float g_mx2[(size_t)B_*M_*OUTC];             // 8 MB  per (b,m,c) max over k
__device__ float g_mn2[(size_t)B_*M_*OUTC];             // 8 MB  per (b,m,c) min over k
__device__ float g_cs1[B_*HID*2];
__device__ float g_cs2[B_*OUTC*2];
__device__ float g_centfb[B_*M_*3];

// ---------------- helpers ----------------
__device__ __forceinline__ unsigned redux_max_u32(unsigned v) {
    unsigned r;
    asm volatile("redux.sync.max.u32 %0, %1, 0xffffffff;" : "=r"(r) : "r"(v));
    return r;
}
__device__ __forceinline__ unsigned redux_min_u32(unsigned v) {
    unsigned r;
    asm volatile("redux.sync.min.u32 %0, %1, 0xffffffff;" : "=r"(r) : "r"(v));
    return r;
}
__device__ __forceinline__ int redux_max_s32(int v) {
    int r;
    asm volatile("redux.sync.max.s32 %0, %1, 0xffffffff;" : "=r"(r) : "r"(v));
    return r;
}

// monotonic total-order key for float (handles negatives from cancellation)
__device__ __forceinline__ unsigned f2key(float f) {
    unsigned u = __float_as_uint(f);
    unsigned mask = ((unsigned)((int)u >> 31)) | 0x80000000u;
    return u ^ mask;
}

__device__ __forceinline__ float2 blk_reduce2(float s, float s2) {
    const int lane = threadIdx.x & 31, w = threadIdx.x >> 5;
    #pragma unroll
    for (int o = 16; o; o >>= 1) {
        s  += __shfl_down_sync(FULLMASK, s,  o);
        s2 += __shfl_down_sync(FULLMASK, s2, o);
    }
    __shared__ float rs[8], rq[8];
    if (lane == 0) { rs[w] = s; rq[w] = s2; }
    __syncthreads();
    if (w == 0) {
        s  = (lane < 8) ? rs[lane] : 0.f;
        s2 = (lane < 8) ? rq[lane] : 0.f;
        #pragma unroll
        for (int o = 4; o; o >>= 1) {
            s  += __shfl_down_sync(FULLMASK, s,  o);
            s2 += __shfl_down_sync(FULLMASK, s2, o);
        }
    }
    return make_float2(s, s2);
}

// ---------------- K1: farthest point sampling ----------------
// 512 threads, 16 points/thread, coords + dist in REGISTERS.
// Every warp redundantly does the block-level reduce (lanes<16 hold warp
// partials); parity double-buffer -> ONE __syncthreads per iteration.
// Tie-break: lowest point index among tied maxima (jnp.argmax semantics).
__global__ void __launch_bounds__(512, 1)
fps_kernel(const float* __restrict__ xyz, float* __restrict__ cent) {
    extern __shared__ float sm[];
    float* xs = sm; float* ys = sm + N_; float* zs = sm + 2 * N_;
    __shared__ unsigned swb[2][16];
    __shared__ unsigned swi[2][16];
    const int b = blockIdx.x, t = threadIdx.x, lane = t & 31, w = t >> 5;
    const float* base = xyz + (size_t)b * N_ * 3;
    for (int p = t; p < N_; p += 512) {
        xs[p] = base[3 * p]; ys[p] = base[3 * p + 1]; zs[p] = base[3 * p + 2];
    }
    __syncthreads();

    float px[16], py[16], pz[16], dist[16];
    #pragma unroll
    for (int j = 0; j < 16; j++) {
        const int p = t + j * 512;
        px[j] = xs[p]; py[j] = ys[p]; pz[j] = zs[p];
        dist[j] = 1e10f;
    }
    float cx = xs[0], cy = ys[0], cz = zs[0];
    if (t == 0) {
        size_t o = (size_t)b * M_ * 3;
        cent[o] = cx; cent[o + 1] = cy; cent[o + 2] = cz;
    }

    for (int it = 1; it < M_; ++it) {
        float mv = -1.f; unsigned mi = 0;
        #pragma unroll
        for (int j = 0; j < 16; j++) {
            // no fma-contraction: match reference mul/add rounding (argmax ties!)
            float dx = __fsub_rn(px[j], cx);
            float dy = __fsub_rn(py[j], cy);
            float dz = __fsub_rn(pz[j], cz);
            float d = __fadd_rn(__fadd_rn(__fmul_rn(dx, dx), __fmul_rn(dy, dy)),
                                __fmul_rn(dz, dz));
            float nd = fminf(dist[j], d);
            dist[j] = nd;
            // strict > keeps smallest p within this thread's ascending-p set
            if (nd > mv) { mv = nd; mi = (unsigned)(t + j * 512); }
        }
        unsigned mb = __float_as_uint(mv);          // dist >= 0 -> bits monotonic
        unsigned wm = redux_max_u32(mb);
        unsigned wi = redux_min_u32((mb == wm) ? mi : 0xFFFFFFFFu);
        const int pb = it & 1;
        if (lane == 0) { swb[pb][w] = wm; swi[pb][w] = wi; }
        __syncthreads();
        unsigned vb = (lane < 16) ? swb[pb][lane] : 0u;
        unsigned vi = (lane < 16) ? swi[pb][lane] : 0xFFFFFFFFu;
        unsigned gm = redux_max_u32(vb);
        unsigned far = redux_min_u32((vb == gm) ? vi : 0xFFFFFFFFu);
        cx = xs[far]; cy = ys[far]; cz = zs[far];
        if (t == 0) {
            size_t o = ((size_t)b * M_ + it) * 3;
            cent[o] = cx; cent[o + 1] = cy; cent[o + 2] = cz;
        }
        // no second barrier: next iteration writes the OTHER parity buffer
    }
}

// ---------------- K2: kNN top-32 (warp per centroid) ----------------
// top_k keeps lowest indices among value ties -> evict HIGHEST index among tied max
__global__ void __launch_bounds__(256, 1)
knn_kernel(const float* __restrict__ xyz, const float* __restrict__ cent) {
    extern __shared__ float sm[];
    float* xs = sm; float* ys = sm + N_; float* zs = sm + 2 * N_; float* xn = sm + 3 * N_;
    const int b = blockIdx.x, cb = blockIdx.y;
    const int t = threadIdx.x, lane = t & 31, w = t >> 5;
    const float* base = xyz + (size_t)b * N_ * 3;
    for (int p = t; p < N_; p += 256) {
        float x = base[3 * p], y = base[3 * p + 1], z = base[3 * p + 2];
        xs[p] = x; ys[p] = y; zs[p] = z;
        xn[p] = x * x + y * y + z * z;
    }
    __syncthreads();

    const int m0 = cb * 64 + w * 8;
    for (int mi = m0; mi < m0 + 8; ++mi) {
        size_t co = ((size_t)b * M_ + mi) * 3;
        float cx = cent[co], cy = cent[co + 1], cz = cent[co + 2];
        float cn = cx * cx + cy * cy + cz * cz;

        unsigned valkey; int vidx;
        {
            int p = lane;
            float d = cn + xn[p] - 2.f * (cx * xs[p] + cy * ys[p] + cz * zs[p]);
            valkey = f2key(d);
            vidx = p;
        }
        unsigned thr = redux_max_u32(valkey);

        for (int c0 = 32; c0 < N_; c0 += 32) {
            int p = c0 + lane;
            float d = cn + xn[p] - 2.f * (cx * xs[p] + cy * ys[p] + cz * zs[p]);
            unsigned dk = f2key(d);
            unsigned pend = __ballot_sync(FULLMASK, dk < thr);
            while (pend) {
                int src = __ffs(pend) - 1;
                pend &= pend - 1;
                unsigned dkj = __shfl_sync(FULLMASK, dk, src);
                if (dkj < thr) {
                    int pj = c0 + src;
                    unsigned vmax = redux_max_u32(valkey);
                    int cand = (valkey == vmax) ? vidx : -1;
                    int victimidx = redux_max_s32(cand);
                    if (valkey == vmax && vidx == victimidx) { valkey = dkj; vidx = pj; }
                    thr = redux_max_u32(valkey);
                }
            }
        }
        g_knn[((size_t)b * M_ + mi) * KK + lane] = vidx;
    }
}

// ---------------- K3: gather + conv1 + in-register stats partials ----------------
__global__ void __launch_bounds__(256, 2)
conv1_kernel(const float* __restrict__ xyz, const float* __restrict__ feat,
             const float* __restrict__ w1, const float* __restrict__ b1,
             const float* __restrict__ cent) {
    __shared__ __align__(16) float Ws[CTOT * 64];   // [cin][cout]
    __shared__ __align__(16) float Xs[CTOT * 68];   // [cin][spatial(64)+pad]
    const int b = blockIdx.y, bx = blockIdx.x, s0 = bx * 64, tid = threadIdx.x;

    for (int i = tid; i < CTOT * 64; i += 256) {
        int cin = i >> 6, c = i & 63;
        Ws[i] = w1[c * CTOT + cin];
    }
    {
        const int ps = tid >> 2, r = tid & 3;
        const int s = s0 + ps, m = s >> 5, kk = s & 31;
        const int idx = g_knn[((size_t)b * M_ + m) * KK + kk];
        const float* fp = feat + ((size_t)b * N_ + idx) * CIN + r * 16;
        #pragma unroll
        for (int q = 0; q < 4; q++) {
            float4 v = *(const float4*)(fp + q * 4);
            int row = 3 + r * 16 + q * 4;
            Xs[(row + 0) * 68 + ps] = v.x;
            Xs[(row + 1) * 68 + ps] = v.y;
            Xs[(row + 2) * 68 + ps] = v.z;
            Xs[(row + 3) * 68 + ps] = v.w;
        }
        if (r == 0) {
            const float* xp = xyz + ((size_t)b * N_ + idx) * 3;
            const float* cp = cent + ((size_t)b * M_ + m) * 3;
            Xs[0 * 68 + ps] = xp[0] - cp[0];
            Xs[1 * 68 + ps] = xp[1] - cp[1];
            Xs[2 * 68 + ps] = xp[2] - cp[2];
        }
    }
    __syncthreads();

    const int ty = tid >> 4, tx = tid & 15;
    float acc[4][4];
    #pragma unroll
    for (int i = 0; i < 4; i++) {
        float bb = b1[ty * 4 + i];
        #pragma unroll
        for (int j = 0; j < 4; j++) acc[i][j] = bb;
    }
    #pragma unroll 4
    for (int cin = 0; cin < CTOT; cin++) {
        float4 a  = *(const float4*)&Ws[cin * 64 + ty * 4];
        float4 bv = *(const float4*)&Xs[cin * 68 + tx * 4];
        acc[0][0] += a.x * bv.x; acc[0][1] += a.x * bv.y; acc[0][2] += a.x * bv.z; acc[0][3] += a.x * bv.w;
        acc[1][0] += a.y * bv.x; acc[1][1] += a.y * bv.y; acc[1][2] += a.y * bv.z; acc[1][3] += a.y * bv.w;
        acc[2][0] += a.z * bv.x; acc[2][1] += a.z * bv.y; acc[2][2] += a.z * bv.z; acc[2][3] += a.z * bv.w;
        acc[3][0] += a.w * bv.x; acc[3][1] += a.w * bv.y; acc[3][2] += a.w * bv.z; acc[3][3] += a.w * bv.w;
    }
    #pragma unroll
    for (int i = 0; i < 4; i++) {
        int c = ty * 4 + i;
        float4 v = make_float4(acc[i][0], acc[i][1], acc[i][2], acc[i][3]);
        *(float4*)&g_x1[((size_t)b * HID + c) * SPAT + s0 + tx * 4] = v;
        // stats partials: sum/sumsq over this block's 64 spatial positions
        float s = (acc[i][0] + acc[i][1]) + (acc[i][2] + acc[i][3]);
        float q = (acc[i][0] * acc[i][0] + acc[i][1] * acc[i][1])
                + (acc[i][2] * acc[i][2] + acc[i][3] * acc[i][3]);
        #pragma unroll
        for (int o = 8; o; o >>= 1) {
            s += __shfl_down_sync(FULLMASK, s, o, 16);
            q += __shfl_down_sync(FULLMASK, q, o, 16);
        }
        if (tx == 0) {
            int pi = ((b * HID + c) * NBLK + bx) * 2;
            g_p1[pi] = s; g_p1[pi + 1] = q;
        }
    }
}

// ---------------- K4/K6: reduce stats partials (tiny, deterministic) ----------------
__global__ void __launch_bounds__(256)
stats1_kernel() {
    const int bid = blockIdx.x;                    // b*HID + c
    float s = 0.f, q = 0.f;
    for (int i = threadIdx.x; i < NBLK; i += 256) {
        s += g_p1[(bid * NBLK + i) * 2];
        q += g_p1[(bid * NBLK + i) * 2 + 1];
    }
    float2 r = blk_reduce2(s, q);
    if (threadIdx.x == 0) { g_cs1[bid * 2] = r.x; g_cs1[bid * 2 + 1] = r.y; }
}

__global__ void __launch_bounds__(256)
stats2_kernel() {
    const int bid = blockIdx.x;                    // b*OUTC + c
    float s = 0.f, q = 0.f;
    for (int i = threadIdx.x; i < NBLK; i += 256) {
        s += g_p2[(bid * NBLK + i) * 2];
        q += g_p2[(bid * NBLK + i) * 2 + 1];
    }
    float2 r = blk_reduce2(s, q);
    if (threadIdx.x == 0) { g_cs2[bid * 2] = r.x; g_cs2[bid * 2 + 1] = r.y; }
}

// ---------------- K5: GN1+ReLU on load + conv2 + in-register max/min + partials ----------------
__global__ void __launch_bounds__(256)
conv2_kernel(const float* __restrict__ w2, const float* __restrict__ b2,
             const float* __restrict__ g1w, const float* __restrict__ g1b) {
    extern __shared__ float dsm[];
    float* Ws2 = dsm;                  // 64*128
    float* Hs  = dsm + HID * OUTC;     // 64*68
    float* sc  = Hs + HID * 68;        // 64
    float* sh  = sc + HID;             // 64
    const int b = blockIdx.y, bx = blockIdx.x, s0 = bx * 64, tid = threadIdx.x;

    for (int i = tid; i < HID * OUTC; i += 256) {
        int cin = i >> 7, c = i & 127;
        Ws2[i] = w2[c * HID + cin];
    }
    if (tid < HID) {
        int c = tid, g = c >> 1, cb = b * HID + g * 2;
        float sum = g_cs1[cb * 2]     + g_cs1[(cb + 1) * 2];
        float sq  = g_cs1[cb * 2 + 1] + g_cs1[(cb + 1) * 2 + 1];
        float inv = 1.0f / 65536.0f;
        float mu = sum * inv;
        float var = sq * inv - mu * mu;
        float a = rsqrtf(var + EPSV) * g1w[c];
        sc[c] = a;
        sh[c] = g1b[c] - mu * a;
    }
    __syncthreads();
    {
        const int c = tid >> 2, sseg = (tid & 3) * 16;
        const float* p = g_x1 + ((size_t)b * HID + c) * SPAT + s0 + sseg;
        float a = sc[c], o = sh[c];
        #pragma unroll
        for (int q = 0; q < 4; q++) {
            float4 v = *(const float4*)(p + q * 4);
            Hs[c * 68 + sseg + q * 4 + 0] = fmaxf(fmaf(v.x, a, o), 0.f);
            Hs[c * 68 + sseg + q * 4 + 1] = fmaxf(fmaf(v.y, a, o), 0.f);
            Hs[c * 68 + sseg + q * 4 + 2] = fmaxf(fmaf(v.z, a, o), 0.f);
            Hs[c * 68 + sseg + q * 4 + 3] = fmaxf(fmaf(v.w, a, o), 0.f);
        }
    }
    __syncthreads();

    const int ty = tid >> 4, tx = tid & 15, c0 = ty * 8;
    float acc[8][4];
    #pragma unroll
    for (int i = 0; i < 8; i++) {
        float bb = b2[c0 + i];
        #pragma unroll
        for (int j = 0; j < 4; j++) acc[i][j] = bb;
    }
    #pragma unroll 4
    for (int cin = 0; cin < HID; cin++) {
        float4 a0 = *(const float4*)&Ws2[cin * OUTC + c0];
        float4 a1 = *(const float4*)&Ws2[cin * OUTC + c0 + 4];
        float4 bv = *(const float4*)&Hs[cin * 68 + tx * 4];
        acc[0][0] += a0.x * bv.x; acc[0][1] += a0.x * bv.y; acc[0][2] += a0.x * bv.z; acc[0][3] += a0.x * bv.w;
        acc[1][0] += a0.y * bv.x; acc[1][1] += a0.y * bv.y; acc[1][2] += a0.y * bv.z; acc[1][3] += a0.y * bv.w;
        acc[2][0] += a0.z * bv.x; acc[2][1] += a0.z * bv.y; acc[2][2] += a0.z * bv.z; acc[2][3] += a0.z * bv.w;
        acc[3][0] += a0.w * bv.x; acc[3][1] += a0.w * bv.y; acc[3][2] += a0.w * bv.z; acc[3][3] += a0.w * bv.w;
        acc[4][0] += a1.x * bv.x; acc[4][1] += a1.x * bv.y; acc[4][2] += a1.x * bv.z; acc[4][3] += a1.x * bv.w;
        acc[5][0] += a1.y * bv.x; acc[5][1] += a1.y * bv.y; acc[5][2] += a1.y * bv.z; acc[5][3] += a1.y * bv.w;
        acc[6][0] += a1.z * bv.x; acc[6][1] += a1.z * bv.y; acc[6][2] += a1.z * bv.z; acc[6][3] += a1.z * bv.w;
        acc[7][0] += a1.w * bv.x; acc[7][1] += a1.w * bv.y; acc[7][2] += a1.w * bv.z; acc[7][3] += a1.w * bv.w;
    }

    // epilogue: per-(c, m) max/min over k (width-8: tx 0-7 = m0, tx 8-15 = m1)
    // + per-channel sum/sumsq partials over the 64-spatial tile (width-16).
    const int m = (s0 >> 5) + (tx >> 3);
    #pragma unroll
    for (int i = 0; i < 8; i++) {
        const int c = c0 + i;
        float mx = fmaxf(fmaxf(acc[i][0], acc[i][1]), fmaxf(acc[i][2], acc[i][3]));
        float mn = fminf(fminf(acc[i][0], acc[i][1]), fminf(acc[i][2], acc[i][3]));
        #pragma unroll
        for (int o = 4; o; o >>= 1) {
            mx = fmaxf(mx, __shfl_down_sync(FULLMASK, mx, o, 8));
            mn = fminf(mn, __shfl_down_sync(FULLMASK, mn, o, 8));
        }
        if ((tx & 7) == 0) {
            g_mx2[((size_t)b * M_ + m) * OUTC + c] = mx;
            g_mn2[((size_t)b * M_ + m) * OUTC + c] = mn;
        }
        float s = (acc[i][0] + acc[i][1]) + (acc[i][2] + acc[i][3]);
        float q = (acc[i][0] * acc[i][0] + acc[i][1] * acc[i][1])
                + (acc[i][2] * acc[i][2] + acc[i][3] * acc[i][3]);
        #pragma unroll
        for (int o = 8; o; o >>= 1) {
            s += __shfl_down_sync(FULLMASK, s, o, 16);
            q += __shfl_down_sync(FULLMASK, q, o, 16);
        }
        if (tx == 0) {
            int pi = ((b * OUTC + c) * NBLK + bx) * 2;
            g_p2[pi] = s; g_p2[pi + 1] = q;
        }
    }
}

// ---------------- K7: GN2 affine on max/min (monotone -> exact) ----------------
__global__ void __launch_bounds__(256)
final_kernel(const float* __restrict__ g2w, const float* __restrict__ g2b,
             float* __restrict__ out) {
    const int b = blockIdx.y;
    const int tid = threadIdx.x;
    const int c = tid & 127;
    const int m = blockIdx.x * 2 + (tid >> 7);
    const int g = c >> 2, cb = b * OUTC + g * 4;
    float sum = 0.f, sq = 0.f;
    #pragma unroll
    for (int q = 0; q < 4; q++) {
        sum += g_cs2[(cb + q) * 2];
        sq  += g_cs2[(cb + q) * 2 + 1];
    }
    const float inv = 1.0f / 131072.0f;
    float mu = sum * inv;
    float var = sq * inv - mu * mu;
    float a = rsqrtf(var + EPSV) * g2w[c];
    float o = g2b[c] - mu * a;
    size_t off = ((size_t)b * M_ + m) * OUTC + c;
    float mx = g_mx2[off], mn = g_mn2[off];
    // y = a*x + o is monotone in x; relu+max over k collapses to one fma
    float v = (a >= 0.f) ? fmaf(mx, a, o) : fmaf(mn, a, o);
    out[off] = fmaxf(v, 0.f);
}

// ---------------- launch ----------------
extern "C" void kernel_launch(void* const* d_in, const int* in_sizes, int n_in,
                              void* d_out, int out_size) {
    const float* xyz  = (const float*)d_in[0];
    const float* feat = (const float*)d_in[1];
    const float* w1   = (const float*)d_in[2];
    const float* b1   = (const float*)d_in[3];
    const float* g1w  = (const float*)d_in[4];
    const float* g1b  = (const float*)d_in[5];
    const float* w2   = (const float*)d_in[6];
    const float* b2   = (const float*)d_in[7];
    const float* g2w  = (const float*)d_in[8];
    const float* g2b  = (const float*)d_in[9];

    float* out = (float*)d_out;
    float* cent;
    float* nf;
    if (out_size == B_ * M_ * 3 + B_ * M_ * OUTC) {
        cent = out;
        nf = out + (size_t)B_ * M_ * 3;
    } else {
        void* p = nullptr;
        cudaGetSymbolAddress(&p, g_centfb);
        cent = (float*)p;
        nf = out;
    }

    cudaFuncSetAttribute(fps_kernel,  cudaFuncAttributeMaxDynamicSharedMemorySize, 3 * N_ * 4);
    cudaFuncSetAttribute(knn_kernel,  cudaFuncAttributeMaxDynamicSharedMemorySize, 4 * N_ * 4);
    cudaFuncSetAttribute(conv2_kernel, cudaFuncAttributeMaxDynamicSharedMemorySize,
                         (HID * OUTC + HID * 68 + 2 * HID) * 4);

    fps_kernel<<<B_, 512, 3 * N_ * 4>>>(xyz, cent);
    knn_kernel<<<dim3(B_, 16), 256, 4 * N_ * 4>>>(xyz, cent);
    conv1_kernel<<<dim3(NBLK, B_), 256>>>(xyz, feat, w1, b1, cent);
    stats1_kernel<<<B_ * HID, 256>>>();
    conv2_kernel<<<dim3(NBLK, B_), 256,
                   (HID * OUTC + HID * 68 + 2 * HID) * 4>>>(w2, b2, g1w, g1b);
    stats2_kernel<<<B_ * OUTC, 256>>>();
    final_kernel<<<dim3(M_ / 2, B_), 256>>>(g2w, g2b, nf);
}